// round 1
// baseline (speedup 1.0000x reference)
#include <cuda_runtime.h>
#include <math.h>

#define NB 32
#define CH 16
#define G  256
#define GG (G*G)

// ---------------- scratch (device globals: allocation-free) ----------------
__device__ float  g_rhat[NB*GG];        // real r_hat (fftshift(ifft2(rsym)) is purely real)
__device__ float2 g_c1[NB*GG];          // FFT scratch / final 1-channel h
__device__ float2 g_c2[NB*GG];          // FFT scratch
__device__ float2 g_bufA[(size_t)NB*CH*GG];   // 268 MB activation ping
__device__ float2 g_bufB[(size_t)NB*CH*GG];   // 268 MB activation pong

// ---------------- 256-pt Stockham radix-2 FFT (128 threads/line) ----------------
// dir=-1: forward (e^{-2pi i nk/N}); dir=+1: inverse kernel (caller applies 1/N scale).
// Data preloaded into s0; caller must __syncthreads() before call; result in s0.
__device__ __forceinline__ void fft256_block(float2* s0, float2* s1, int t, float dir)
{
    float2* src = s0; float2* dst = s1;
#pragma unroll
    for (int s = 0; s < 8; s++) {
        int Ns = 1 << s;
        int jm = t & (Ns - 1);
        float2 a = src[t];
        float2 b = src[t + 128];
        float ang = dir * 3.14159265358979323846f * (float)jm / (float)Ns;
        float sn, cs;
        sincosf(ang, &sn, &cs);
        float2 bt = make_float2(b.x*cs - b.y*sn, b.x*sn + b.y*cs);
        int id = ((t >> s) << (s + 1)) | jm;
        dst[id]      = make_float2(a.x + bt.x, a.y + bt.y);
        dst[id + Ns] = make_float2(a.x - bt.x, a.y - bt.y);
        __syncthreads();
        float2* tt = src; src = dst; dst = tt;
    }
}

// ---------------- ifft2 of rsym, pass A (over n, expansion on the fly) ----------------
// writes transposed + v-shifted: g_c1[b][(v+128)&255][m]
__global__ void ifft_passA_kernel(const float* __restrict__ r)
{
    __shared__ float2 bA[256], bB[256];
    const int m = blockIdx.x, b = blockIdx.y, t = threadIdx.x;

    if (m == 0 || m == 128) {
        g_c1[(size_t)b*GG + (size_t)t*256 + m]        = make_float2(0.f, 0.f);
        g_c1[(size_t)b*GG + (size_t)(t+128)*256 + m]  = make_float2(0.f, 0.f);
        return;
    }
    const float sm = (m < 128) ? 1.f : -1.f;
    const int   im = (m < 128) ? (m - 1) : (255 - m);
    const float* rrow = r + ((size_t)b*127 + im)*127;

#pragma unroll
    for (int k = 0; k < 2; k++) {
        int n = t + k*128;
        float v = 0.f;
        if (n != 0 && n != 128)
            v = (n < 128) ? rrow[n-1] : -rrow[255-n];
        bA[n] = make_float2(sm * v, 0.f);
    }
    __syncthreads();
    fft256_block(bA, bB, t, +1.0f);
    const float sc = 1.0f / 256.0f;
    for (int k = t; k < 256; k += 128) {
        float2 v = bA[k];
        g_c1[(size_t)b*GG + (size_t)((k+128)&255)*256 + m] = make_float2(v.x*sc, v.y*sc);
    }
}

// ---------------- ifft2 pass B (over m) + fftshift(u) + take real ----------------
__global__ void ifft_passB_kernel()
{
    __shared__ float2 bA[256], bB[256];
    const int vp = blockIdx.x, b = blockIdx.y, t = threadIdx.x;
    const size_t base = (size_t)b*GG + (size_t)vp*256;
    bA[t]     = g_c1[base + t];
    bA[t+128] = g_c1[base + t + 128];
    __syncthreads();
    fft256_block(bA, bB, t, +1.0f);
    const float sc = 1.0f / 256.0f;
    for (int u = t; u < 256; u += 128)
        g_rhat[(size_t)b*GG + (size_t)((u+128)&255)*256 + vp] = bA[u].x * sc;
}

// ---------------- conv1: real r_hat [B,256,256] x complex w1 -> bufA [B,16,256,256] ----------------
__global__ void __launch_bounds__(256) conv1_kernel(
    const float* __restrict__ w1r, const float* __restrict__ w1i,
    float2* __restrict__ out)
{
    __shared__ float  sX[34*34];
    __shared__ float2 sW[CH*9];
    const int b  = blockIdx.z;
    const int bx = blockIdx.x*32 - 1;
    const int by = blockIdx.y*32 - 1;
    const int tid = threadIdx.x;

    for (int idx = tid; idx < 34*34; idx += 256) {
        int yy = idx / 34, xx = idx - yy*34;
        int gy = by + yy, gx = bx + xx;
        float v = 0.f;
        if ((unsigned)gy < 256u && (unsigned)gx < 256u)
            v = g_rhat[(size_t)b*GG + gy*256 + gx];
        sX[idx] = v;
    }
    if (tid < CH*9) {
        int off = b*(CH*9) + tid;          // w1: [B,16,1,3,3]
        sW[tid] = make_float2(w1r[off], w1i[off]);
    }
    __syncthreads();

    const int qx = tid & 15, qy = tid >> 4;
    const int px0 = qx*2, py0 = qy*2;
    float p[4][4];
#pragma unroll
    for (int yy = 0; yy < 4; yy++)
#pragma unroll
        for (int xx = 0; xx < 4; xx++)
            p[yy][xx] = sX[(py0+yy)*34 + px0+xx];

#pragma unroll 1
    for (int half = 0; half < 2; half++) {
        float ar[8][4], ai[8][4];
#pragma unroll
        for (int c = 0; c < 8; c++)
#pragma unroll
            for (int q = 0; q < 4; q++) { ar[c][q] = 0.f; ai[c][q] = 0.f; }

#pragma unroll
        for (int k = 0; k < 9; k++) {
            int dy = k/3, dx = k - dy*3;
#pragma unroll
            for (int c = 0; c < 8; c++) {
                float2 w = sW[(half*8 + c)*9 + k];
#pragma unroll
                for (int iy = 0; iy < 2; iy++)
#pragma unroll
                    for (int ix = 0; ix < 2; ix++) {
                        float x = p[dy+iy][dx+ix];
                        ar[c][iy*2+ix] = fmaf(w.x, x, ar[c][iy*2+ix]);
                        ai[c][iy*2+ix] = fmaf(w.y, x, ai[c][iy*2+ix]);
                    }
            }
        }
#pragma unroll
        for (int c = 0; c < 8; c++) {
            int co = half*8 + c;
            float2* ob = out + (size_t)(b*CH + co)*GG;
#pragma unroll
            for (int iy = 0; iy < 2; iy++) {
                int oy = by + 1 + py0 + iy;
                int ox = bx + 1 + px0;
                float4 v4 = make_float4(ar[c][iy*2+0], ai[c][iy*2+0],
                                        ar[c][iy*2+1], ai[c][iy*2+1]);
                *(float4*)(ob + (size_t)oy*256 + ox) = v4;
            }
        }
    }
}

// ---------------- main complex 16->16 conv (optionally adjoint weights, fused wtheta) ----------------
template<bool ADJ, bool WT>
__global__ void __launch_bounds__(256, 1) conv16_kernel(
    const float2* __restrict__ in, float2* __restrict__ out,
    const float* __restrict__ wr, const float* __restrict__ wi,
    const float* __restrict__ wtr, const float* __restrict__ wti)
{
    extern __shared__ float2 dynS[];
    float2* sIn = dynS;                     // [16][34][34]
    float2* sW  = dynS + CH*34*34;          // [co][ci][9]
    const int b  = blockIdx.z;
    const int bx = blockIdx.x*32 - 1;
    const int by = blockIdx.y*32 - 1;
    const int tid = threadIdx.x;

    for (int idx = tid; idx < CH*CH*9; idx += 256) {
        int co = idx / (CH*9);
        int ci = (idx / 9) % CH;
        int k  = idx % 9;
        float vr, vi;
        if (!ADJ) {
            int off = ((b*CH + co)*CH + ci)*9 + k;
            vr = wr[off]; vi = wi[off];
        } else {
            int dy = k/3, dx = k - dy*3;
            int off = ((b*CH + ci)*CH + co)*9 + dx*3 + dy;  // conj(w[b,ci,co,dx,dy])
            vr = wr[off]; vi = -wi[off];
        }
        sW[idx] = make_float2(vr, vi);
    }
    const float2* inb = in + (size_t)b*CH*GG;
    for (int idx = tid; idx < CH*34*34; idx += 256) {
        int ci  = idx / (34*34);
        int rem = idx - ci*(34*34);
        int yy  = rem / 34;
        int xx  = rem - yy*34;
        int gy = by + yy, gx = bx + xx;
        float2 v = make_float2(0.f, 0.f);
        if ((unsigned)gy < 256u && (unsigned)gx < 256u)
            v = inb[ci*GG + gy*256 + gx];
        sIn[idx] = v;
    }
    __syncthreads();

    const int qx = tid & 15, qy = tid >> 4;
    const int px0 = qx*2, py0 = qy*2;

#pragma unroll 1
    for (int half = 0; half < 2; half++) {
        float ar[8][4], ai[8][4];
#pragma unroll
        for (int c = 0; c < 8; c++)
#pragma unroll
            for (int q = 0; q < 4; q++) { ar[c][q] = 0.f; ai[c][q] = 0.f; }

#pragma unroll 1
        for (int ci = 0; ci < CH; ci++) {
            float2 p[4][4];
            const float2* base = sIn + ci*(34*34) + py0*34 + px0;
#pragma unroll
            for (int yy = 0; yy < 4; yy++)
#pragma unroll
                for (int xx = 0; xx < 4; xx++)
                    p[yy][xx] = base[yy*34 + xx];
            const float2* wb = sW + ci*9 + (half*8)*(CH*9);
#pragma unroll
            for (int k = 0; k < 9; k++) {
                int dy = k/3, dx = k - dy*3;
#pragma unroll
                for (int c = 0; c < 8; c++) {
                    float2 w = wb[c*(CH*9) + k];
#pragma unroll
                    for (int iy = 0; iy < 2; iy++)
#pragma unroll
                        for (int ix = 0; ix < 2; ix++) {
                            float2 x = p[dy+iy][dx+ix];
                            float& rr = ar[c][iy*2+ix];
                            float& ii = ai[c][iy*2+ix];
                            rr = fmaf(w.x, x.x, fmaf(-w.y, x.y, rr));
                            ii = fmaf(w.x, x.y, fmaf( w.y, x.x, ii));
                        }
                }
            }
        }
#pragma unroll
        for (int c = 0; c < 8; c++) {
            int co = half*8 + c;
            size_t chb = (size_t)(b*CH + co)*GG;
#pragma unroll
            for (int iy = 0; iy < 2; iy++) {
                int oy = by + 1 + py0 + iy;
                int ox = bx + 1 + px0;
                size_t o = chb + (size_t)oy*256 + ox;
                float2 h0 = make_float2(ar[c][iy*2+0], ai[c][iy*2+0]);
                float2 h1 = make_float2(ar[c][iy*2+1], ai[c][iy*2+1]);
                if (WT) {
                    float2 tr = *(const float2*)(wtr + o);
                    float2 ti = *(const float2*)(wti + o);
                    float2 n0 = make_float2(h0.x*tr.x - h0.y*ti.x, h0.x*ti.x + h0.y*tr.x);
                    float2 n1 = make_float2(h1.x*tr.y - h1.y*ti.y, h1.x*ti.y + h1.y*tr.y);
                    h0 = n0; h1 = n1;
                }
                *(float4*)(out + o) = make_float4(h0.x, h0.y, h1.x, h1.y);
            }
        }
    }
}

// ---------------- conv 16->1 with adj(w1), writes g_c1 ----------------
__global__ void __launch_bounds__(256, 1) conv_adj1_kernel(
    const float2* __restrict__ in,
    const float* __restrict__ w1r, const float* __restrict__ w1i)
{
    extern __shared__ float2 dynS[];
    float2* sIn = dynS;                 // [16][34][34]
    __shared__ float2 sW[CH*9];
    const int b  = blockIdx.z;
    const int bx = blockIdx.x*32 - 1;
    const int by = blockIdx.y*32 - 1;
    const int tid = threadIdx.x;

    if (tid < CH*9) {
        int ci = tid / 9, k = tid % 9;
        int dy = k/3, dx = k - dy*3;
        int off = (b*CH + ci)*9 + dx*3 + dy;   // conj(w1[b,ci,0,dx,dy])
        sW[tid] = make_float2(w1r[off], -w1i[off]);
    }
    const float2* inb = in + (size_t)b*CH*GG;
    for (int idx = tid; idx < CH*34*34; idx += 256) {
        int ci  = idx / (34*34);
        int rem = idx - ci*(34*34);
        int yy  = rem / 34;
        int xx  = rem - yy*34;
        int gy = by + yy, gx = bx + xx;
        float2 v = make_float2(0.f, 0.f);
        if ((unsigned)gy < 256u && (unsigned)gx < 256u)
            v = inb[ci*GG + gy*256 + gx];
        sIn[idx] = v;
    }
    __syncthreads();

    const int qx = tid & 15, qy = tid >> 4;
    const int px0 = qx*2, py0 = qy*2;
    float ar[4] = {0.f,0.f,0.f,0.f}, ai[4] = {0.f,0.f,0.f,0.f};

#pragma unroll 1
    for (int ci = 0; ci < CH; ci++) {
        float2 p[4][4];
        const float2* base = sIn + ci*(34*34) + py0*34 + px0;
#pragma unroll
        for (int yy = 0; yy < 4; yy++)
#pragma unroll
            for (int xx = 0; xx < 4; xx++)
                p[yy][xx] = base[yy*34 + xx];
#pragma unroll
        for (int k = 0; k < 9; k++) {
            int dy = k/3, dx = k - dy*3;
            float2 w = sW[ci*9 + k];
#pragma unroll
            for (int iy = 0; iy < 2; iy++)
#pragma unroll
                for (int ix = 0; ix < 2; ix++) {
                    float2 x = p[dy+iy][dx+ix];
                    ar[iy*2+ix] = fmaf(w.x, x.x, fmaf(-w.y, x.y, ar[iy*2+ix]));
                    ai[iy*2+ix] = fmaf(w.x, x.y, fmaf( w.y, x.x, ai[iy*2+ix]));
                }
        }
    }
#pragma unroll
    for (int iy = 0; iy < 2; iy++) {
        int oy = by + 1 + py0 + iy;
        int ox = bx + 1 + px0;
        *(float4*)(g_c1 + (size_t)b*GG + (size_t)oy*256 + ox) =
            make_float4(ar[iy*2+0], ai[iy*2+0], ar[iy*2+1], ai[iy*2+1]);
    }
}

// ---------------- forward fft2 with ifftshift on input ----------------
__global__ void fft_passA_kernel()
{
    __shared__ float2 bA[256], bB[256];
    const int m = blockIdx.x, b = blockIdx.y, t = threadIdx.x;
    const int msrc = (m + 128) & 255;
    const size_t base = (size_t)b*GG + (size_t)msrc*256;
    for (int k = t; k < 256; k += 128)
        bA[k] = g_c1[base + ((k + 128) & 255)];
    __syncthreads();
    fft256_block(bA, bB, t, -1.0f);
    for (int q = t; q < 256; q += 128)
        g_c2[(size_t)b*GG + (size_t)q*256 + m] = bA[q];
}

__global__ void fft_passB_kernel(float* __restrict__ out)
{
    __shared__ float2 bA[256], bB[256];
    const int q = blockIdx.x, b = blockIdx.y, t = threadIdx.x;   // q < 127
    const size_t base = (size_t)b*GG + (size_t)q*256;
    bA[t]     = g_c2[base + t];
    bA[t+128] = g_c2[base + t + 128];
    __syncthreads();
    fft256_block(bA, bB, t, -1.0f);
    for (int p = t; p < 256; p += 128)
        if (p < 127)
            out[((size_t)b*127 + p)*127 + q] = bA[p].x;
}

// ---------------- launch ----------------
extern "C" void kernel_launch(void* const* d_in, const int* in_sizes, int n_in,
                              void* d_out, int out_size)
{
    (void)in_sizes; (void)n_in; (void)out_size;
    const float* r   = (const float*)d_in[0];
    const float* w1r = (const float*)d_in[1];
    const float* w1i = (const float*)d_in[2];
    const float* w2r = (const float*)d_in[3];
    const float* w2i = (const float*)d_in[4];
    const float* w3r = (const float*)d_in[5];
    const float* w3i = (const float*)d_in[6];
    const float* wtr = (const float*)d_in[7];
    const float* wti = (const float*)d_in[8];
    float* out = (float*)d_out;

    void *pA = nullptr, *pB = nullptr;
    cudaGetSymbolAddress(&pA, g_bufA);
    cudaGetSymbolAddress(&pB, g_bufB);
    float2* bufA = (float2*)pA;
    float2* bufB = (float2*)pB;

    const int SMEM16 = (CH*34*34 + CH*CH*9) * (int)sizeof(float2);   // 166,400 B
    const int SMEMA1 = (CH*34*34) * (int)sizeof(float2);             // 147,968 B
    cudaFuncSetAttribute(conv16_kernel<false,false>, cudaFuncAttributeMaxDynamicSharedMemorySize, SMEM16);
    cudaFuncSetAttribute(conv16_kernel<false,true >, cudaFuncAttributeMaxDynamicSharedMemorySize, SMEM16);
    cudaFuncSetAttribute(conv16_kernel<true ,false>, cudaFuncAttributeMaxDynamicSharedMemorySize, SMEM16);
    cudaFuncSetAttribute(conv_adj1_kernel,           cudaFuncAttributeMaxDynamicSharedMemorySize, SMEMA1);

    dim3 gfft(256, NB);
    ifft_passA_kernel<<<gfft, 128>>>(r);
    ifft_passB_kernel<<<gfft, 128>>>();

    dim3 gconv(8, 8, NB);
    conv1_kernel<<<gconv, 256>>>(w1r, w1i, bufA);
    conv16_kernel<false,false><<<gconv, 256, SMEM16>>>(bufA, bufB, w2r, w2i, nullptr, nullptr);
    conv16_kernel<false,true ><<<gconv, 256, SMEM16>>>(bufB, bufA, w3r, w3i, wtr, wti);
    conv16_kernel<true ,false><<<gconv, 256, SMEM16>>>(bufA, bufB, w3r, w3i, nullptr, nullptr);
    conv16_kernel<true ,false><<<gconv, 256, SMEM16>>>(bufB, bufA, w2r, w2i, nullptr, nullptr);
    conv_adj1_kernel<<<gconv, 256, SMEMA1>>>(bufA, w1r, w1i);

    fft_passA_kernel<<<gfft, 128>>>();
    dim3 gfftB(127, NB);
    fft_passB_kernel<<<gfftB, 128>>>(out);
}